// round 2
// baseline (speedup 1.0000x reference)
#include <cuda_runtime.h>
#include <cstdint>

// Problem constants
#define BB 8
#define HH 256
#define WW 256
#define CC 32     // in channels = out channels
#define KK 16     // kept rfft bins along W
// h-mode set: {0..15} U {240..255} -> 32 modes, paired as (m, 256-m)

// Scratch (static device allocations are allowed)
__device__ float2 g_X1[BB * KK * HH * CC];   // [b][k][y][c]  fwd W-DFT result
__device__ float2 g_G [BB * HH * KK * CC];   // [b][y][k][o]  scaled spectral rows for inverse W
__device__ float2 g_Wt[KK * 32 * CC * CC];   // [k][h'][c][o] reordered complex weights

// ---------------------------------------------------------------------------
// Kernel 0: reorder weights  w_real/w_imag[w][i][o][m1][m2] -> Wt[k][h'][c][o]
//   h' = w*16 + m1, k = m2, c = i
// ---------------------------------------------------------------------------
__global__ void k0_reorder_w(const float* __restrict__ wr, const float* __restrict__ wi) {
    int idx = blockIdx.x * 256 + threadIdx.x;          // 0 .. 524287
    int o  = idx & 31;
    int c  = (idx >> 5) & 31;
    int hp = (idx >> 10) & 31;
    int k  = idx >> 15;
    int w  = hp >> 4;
    int m1 = hp & 15;
    int src = (((w * 32 + c) * 32 + o) * 16 + m1) * 16 + k;
    g_Wt[idx] = make_float2(wr[src], wi[src]);
}

// ---------------------------------------------------------------------------
// Kernel 1: forward W-DFT per (b,y) row.
//   X1[b,k,y,c] = sum_x x[b,y,x,c] * e^{-2*pi*i*k*x/256},  k = 0..15
//   Symmetry: s_x = v_x + v_{256-x}, d_x = v_x - v_{256-x}:
//     re = v0 + (-1)^k v128 + sum_{x=1..127} s_x cos(kx)
//     im =                  - sum_{x=1..127} d_x sin(kx)
// ---------------------------------------------------------------------------
__global__ void k1_fwd_w(const float* __restrict__ x) {
    __shared__ float xs[HH * CC];        // 32 KB
    __shared__ float ctab[256], stab[256];
    int t = threadIdx.x;
    int bid = blockIdx.x;                // b*256 + y

    {
        float ang = 6.28318530717958647692f * (float)t / 256.0f;
        float s, c0;
        sincosf(ang, &s, &c0);
        ctab[t] = c0; stab[t] = s;
    }

    // load row tile [256 x][32 c], coalesced float4
    const float4* xin = (const float4*)(x + (size_t)bid * (WW * CC));
    float4* xs4 = (float4*)xs;
#pragma unroll
    for (int i = t; i < (WW * CC) / 4; i += 256) xs4[i] = xin[i];
    __syncthreads();

    // in-place sum/diff: xs[x'] <- s, xs[256-x'] <- d   (x' = 1..127)
    for (int tt = t; tt < 127 * 32; tt += 256) {
        int xp = (tt >> 5) + 1, c = tt & 31;
        float a = xs[xp * 32 + c];
        float b = xs[(256 - xp) * 32 + c];
        xs[xp * 32 + c]        = a + b;
        xs[(256 - xp) * 32 + c] = a - b;
    }
    __syncthreads();

    int c  = t & 31;
    int k1 = t >> 5;        // 0..7  (warp-uniform)
    int k2 = k1 + 8;

    float v0   = xs[c];
    float v128 = xs[128 * 32 + c];
    float sgn  = (k1 & 1) ? -1.0f : 1.0f;   // (-1)^{k1} == (-1)^{k2}
    float base = v0 + sgn * v128;
    float re1 = base, im1 = 0.0f;
    float re2 = base, im2 = 0.0f;

    int i1 = 0, i2 = 0;
#pragma unroll 4
    for (int xp = 1; xp <= 127; xp++) {
        i1 = (i1 + k1) & 255;
        i2 = (i2 + k2) & 255;
        float sv = xs[xp * 32 + c];
        float dv = xs[(256 - xp) * 32 + c];
        re1 = fmaf(sv,  ctab[i1], re1);
        im1 = fmaf(-dv, stab[i1], im1);
        re2 = fmaf(sv,  ctab[i2], re2);
        im2 = fmaf(-dv, stab[i2], im2);
    }

    int b = bid >> 8, y = bid & 255;
    g_X1[((b * 16 + k1) * 256 + y) * 32 + c] = make_float2(re1, im1);
    g_X1[((b * 16 + k2) * 256 + y) * 32 + c] = make_float2(re2, im2);
}

// ---------------------------------------------------------------------------
// Kernel 2: per (b,k):  forward H-DFT (32 kept modes) -> einsum -> inverse H.
//   Writes g_G[b][y][k][o] = c_k/(H*W) * sum_{h in S} OB[h][o] e^{+2*pi*i*h*y/256}
// ---------------------------------------------------------------------------
__global__ void k2_mid() {
    __shared__ float2 X2[32 * 32];      // [h'][c]
    __shared__ float2 OB[32 * 32];      // [h'][o]
    __shared__ float2 Ssh[17 * 32];     // [p][o]
    __shared__ float2 Dsh[17 * 32];
    __shared__ float ctab[256], stab[256];

    int t = threadIdx.x;
    int b = blockIdx.x >> 4;
    int k = blockIdx.x & 15;

    {
        float ang = 6.28318530717958647692f * (float)t / 256.0f;
        float s, c0;
        sincosf(ang, &s, &c0);
        ctab[t] = c0; stab[t] = s;
    }
    __syncthreads();

    // --- Step A: P_m,Q_m over y (m = 0..16), streamed from global (L1 reuse) ---
    const float2* __restrict__ xv = g_X1 + (size_t)(b * 16 + k) * 256 * 32; // [y][c]
    for (int tt = t; tt < 17 * 32; tt += 256) {
        int m = tt >> 5, cc = tt & 31;
        float Pr = 0.f, Pi = 0.f, Qr = 0.f, Qi = 0.f;
        int idx = 0;
#pragma unroll 4
        for (int y = 0; y < 256; y++) {
            float2 v = xv[y * 32 + cc];
            float cs = ctab[idx], sn = stab[idx];
            idx = (idx + m) & 255;
            Pr = fmaf(v.x, cs, Pr);
            Pi = fmaf(v.y, cs, Pi);
            Qr = fmaf(v.x, sn, Qr);
            Qi = fmaf(v.y, sn, Qi);
        }
        // map to the 32 kept modes:
        //  h' = m (0..15):        X2 = P - iQ
        //  h' = 32-m (17..31):    X2 = P + iQ   (m = 1..15)
        //  h' = 16 (h=240, m=16): X2 = P + iQ
        if (m == 0) {
            X2[0 * 32 + cc] = make_float2(Pr + Qi, Pi - Qr);
        } else if (m == 16) {
            X2[16 * 32 + cc] = make_float2(Pr - Qi, Pi + Qr);
        } else {
            X2[m * 32 + cc]        = make_float2(Pr + Qi, Pi - Qr);
            X2[(32 - m) * 32 + cc] = make_float2(Pr - Qi, Pi + Qr);
        }
    }
    __syncthreads();

    // --- Step B: einsum over c:  OB[h'][o] = sum_c X2[h'][c] * Wt[k][h'][c][o] ---
    const float2* __restrict__ wtk = g_Wt + (size_t)k * 32 * 32 * 32;
    for (int tt = t; tt < 1024; tt += 256) {
        int hp = tt >> 5, o = tt & 31;
        const float2* __restrict__ wrow = wtk + hp * 1024 + o;   // stride 32 (float2)
        const float2* __restrict__ xrow = X2 + hp * 32;
        float ar = 0.f, ai = 0.f;
#pragma unroll 8
        for (int cc = 0; cc < 32; cc++) {
            float2 xx = xrow[cc];
            float2 ww = wrow[cc * 32];
            ar = fmaf(xx.x, ww.x, ar); ar = fmaf(-xx.y, ww.y, ar);
            ai = fmaf(xx.x, ww.y, ai); ai = fmaf( xx.y, ww.x, ai);
        }
        OB[hp * 32 + o] = make_float2(ar, ai);
    }
    __syncthreads();

    // --- Step C: pair-combine for inverse H:  p=0..16 ---
    //  pair (h=p, h=256-p): S = OB[p]+OB[32-p], D = OB[p]-OB[32-p]
    //  p=0  (h=0):   S=OB0, D=-OB0 (sin term exactly 0)
    //  p=16 (h=240): e^{+2 pi i 240 y/256} = e^{-i * (2 pi 16 y/256)} -> S=OB16, D=-OB16
    for (int tt = t; tt < 17 * 32; tt += 256) {
        int p = tt >> 5, o = tt & 31;
        float2 A = OB[p * 32 + o];
        float2 S, Dd;
        if (p == 0 || p == 16) {
            S = A; Dd = make_float2(-A.x, -A.y);
        } else {
            float2 Bv = OB[(32 - p) * 32 + o];
            S  = make_float2(A.x + Bv.x, A.y + Bv.y);
            Dd = make_float2(A.x - Bv.x, A.y - Bv.y);
        }
        Ssh[p * 32 + o] = S;
        Dsh[p * 32 + o] = Dd;
    }
    __syncthreads();

    // --- Step D: inverse-H to all 256 y, scaled write of g_G ---
    float sc = (k == 0) ? (1.0f / 65536.0f) : (2.0f / 65536.0f);
    int o  = t & 31;
    int yb = t >> 5;    // warp-uniform
#pragma unroll 4
    for (int j = 0; j < 32; j++) {
        int y = yb + 8 * j;
        float gr = 0.f, gi = 0.f;
        int idx = 0;
#pragma unroll
        for (int p = 0; p <= 16; p++) {
            float cs = ctab[idx], sn = stab[idx];
            idx = (idx + y) & 255;
            float2 S  = Ssh[p * 32 + o];
            float2 Dd = Dsh[p * 32 + o];
            gr = fmaf(S.x, cs, gr); gr = fmaf(-Dd.y, sn, gr);
            gi = fmaf(S.y, cs, gi); gi = fmaf( Dd.x, sn, gi);
        }
        g_G[((size_t)(b * 256 + y) * 16 + k) * 32 + o] = make_float2(gr * sc, gi * sc);
    }
}

// ---------------------------------------------------------------------------
// Kernel 3: inverse W per (b,y) row; writes channels_last output.
//   out[x]     = A - B,  out[256-x] = A + B
//   A = sum_k Gr[k] cos(2 pi k x/256),  B = sum_k Gi[k] sin(...)
// ---------------------------------------------------------------------------
__global__ void k3_inv_w(float* __restrict__ out) {
    __shared__ float ctab[256], stab[256];
    int t = threadIdx.x;
    {
        float ang = 6.28318530717958647692f * (float)t / 256.0f;
        float s, c0;
        sincosf(ang, &s, &c0);
        ctab[t] = c0; stab[t] = s;
    }
    __syncthreads();

    int bid = blockIdx.x;                         // b*256 + y
    const float2* __restrict__ g = g_G + (size_t)bid * (KK * CC);
    int o = t & 31;
    int w = t >> 5;                               // warp id, uniform

    float Gr[16], Gi[16];
#pragma unroll
    for (int k = 0; k < 16; k++) {
        float2 v = g[k * 32 + o];                 // coalesced per k
        Gr[k] = v.x; Gi[k] = v.y;
    }

    float* __restrict__ ob = out + (size_t)bid * (WW * CC);
    for (int xp = w; xp <= 128; xp += 8) {
        float A = 0.f, B = 0.f;
        int idx = 0;
#pragma unroll
        for (int k = 0; k < 16; k++) {
            float cs = ctab[idx], sn = stab[idx];
            idx = (idx + xp) & 255;
            A = fmaf(Gr[k], cs, A);
            B = fmaf(Gi[k], sn, B);
        }
        ob[xp * 32 + o] = A - B;
        if (xp != 0 && xp != 128)
            ob[(256 - xp) * 32 + o] = A + B;
    }
}

// ---------------------------------------------------------------------------
extern "C" void kernel_launch(void* const* d_in, const int* in_sizes, int n_in,
                              void* d_out, int out_size) {
    const float* x  = (const float*)d_in[0];
    const float* wr = (const float*)d_in[1];
    const float* wi = (const float*)d_in[2];
    float* out = (float*)d_out;

    k0_reorder_w<<<2048, 256>>>(wr, wi);
    k1_fwd_w   <<<BB * HH, 256>>>(x);
    k2_mid     <<<BB * KK, 256>>>();
    k3_inv_w   <<<BB * HH, 256>>>(out);
}

// round 3
// speedup vs baseline: 1.7174x; 1.7174x over previous
#include <cuda_runtime.h>
#include <cstdint>

#define BB 8

// Scratch
__device__ float2 g_X1[BB * 16 * 256 * 32];   // [b][k][y][c]
__device__ float2 g_G [BB * 256 * 16 * 32];   // [b][y][k][o]
__device__ float2 g_Wt[16 * 32 * 32 * 32];    // [k][h'][c][o]

// ---------------------------------------------------------------------------
// Compile-time trig table (double Taylor, quadrant-reduced). Used only with
// compile-time indices after full unroll -> folds to FFMA immediates.
// ---------------------------------------------------------------------------
struct Trig { float c[256]; float s[256]; };

__host__ __device__ constexpr double tp_cos(double x) {
    double x2 = x * x, t = 1.0, s = 1.0;
    for (int n = 1; n <= 12; n++) { t *= -x2 / double((2 * n - 1) * (2 * n)); s += t; }
    return s;
}
__host__ __device__ constexpr double tp_sin(double x) {
    double x2 = x * x, t = x, s = x;
    for (int n = 1; n <= 12; n++) { t *= -x2 / double((2 * n) * (2 * n + 1)); s += t; }
    return s;
}
__host__ __device__ constexpr Trig make_trig() {
    Trig tr{};
    for (int i = 0; i < 256; i++) {
        int q = i >> 6, r = i & 63;
        double x = 3.14159265358979323846 * double(r) / 128.0;
        double c = tp_cos(x), s = tp_sin(x);
        tr.c[i] = (float)(q == 0 ? c : q == 1 ? -s : q == 2 ? -c :  s);
        tr.s[i] = (float)(q == 0 ? s : q == 1 ?  c : q == 2 ? -s : -c);
    }
    return tr;
}

// ---------------------------------------------------------------------------
// k0: reorder weights  w[w][i][o][m1][m2] -> Wt[k][h'][c][o],  h'=w*16+m1, k=m2
// ---------------------------------------------------------------------------
__global__ void k0_reorder_w(const float* __restrict__ wr, const float* __restrict__ wi) {
    int idx = blockIdx.x * 256 + threadIdx.x;
    int o  = idx & 31;
    int c  = (idx >> 5) & 31;
    int hp = (idx >> 10) & 31;
    int k  = idx >> 15;
    int w  = hp >> 4;
    int m1 = hp & 15;
    int src = (((w * 32 + c) * 32 + o) * 16 + m1) * 16 + k;
    g_Wt[idx] = make_float2(wr[src], wi[src]);
}

// ---------------------------------------------------------------------------
// k1: forward W-DFT. Warp per row (b,y), lane = c, 16 k-bins in registers.
// ---------------------------------------------------------------------------
__global__ void __launch_bounds__(256) k1_fwd_w(const float* __restrict__ x) {
    constexpr Trig TR = make_trig();
    int t = threadIdx.x, c = t & 31;
    int row = blockIdx.x * 8 + (t >> 5);
    const float* __restrict__ p = x + (size_t)row * 8192 + c;

    float re[16], im[16];
    float v0 = p[0], v128 = p[128 * 32];
    float pe = v0 + v128, po = v0 - v128;
#pragma unroll
    for (int k = 0; k < 16; k++) { re[k] = (k & 1) ? po : pe; im[k] = 0.f; }

#pragma unroll
    for (int xp = 1; xp <= 127; xp++) {
        float a = p[xp * 32];
        float b = p[(256 - xp) * 32];
        float s = a + b, d = a - b;
#pragma unroll
        for (int k = 0; k < 16; k++) {
            const int id = (k * xp) & 255;
            re[k] = fmaf(s, TR.c[id], re[k]);
            if (k) im[k] = fmaf(d, -TR.s[id], im[k]);
        }
    }

    int b_ = row >> 8, y = row & 255;
    float2* o = g_X1 + ((size_t)(b_ * 16) * 256 + y) * 32 + c;
#pragma unroll
    for (int k = 0; k < 16; k++) o[(size_t)k * 8192] = make_float2(re[k], im[k]);
}

// ---------------------------------------------------------------------------
// k2 helpers
// ---------------------------------------------------------------------------
template<int M0, int MC>
__device__ __forceinline__ void phaseA(const float2* __restrict__ xv,
                                       float2* __restrict__ X2, int c) {
    constexpr Trig TR = make_trig();
    float Pr[MC], Pi[MC], Qr[MC], Qi[MC];
    float2 v0 = xv[c], v128 = xv[128 * 32 + c];
#pragma unroll
    for (int j = 0; j < MC; j++) {
        const int m = M0 + 8 * j;
        Pr[j] = (m & 1) ? v0.x - v128.x : v0.x + v128.x;
        Pi[j] = (m & 1) ? v0.y - v128.y : v0.y + v128.y;
        Qr[j] = 0.f; Qi[j] = 0.f;
    }
#pragma unroll
    for (int yp = 1; yp <= 127; yp++) {
        float2 a = xv[yp * 32 + c];
        float2 b = xv[(256 - yp) * 32 + c];
        float sx = a.x + b.x, sy = a.y + b.y;
        float dx = a.x - b.x, dy = a.y - b.y;
#pragma unroll
        for (int j = 0; j < MC; j++) {
            const int m = M0 + 8 * j, id = (m * yp) & 255;
            Pr[j] = fmaf(sx, TR.c[id], Pr[j]);
            Pi[j] = fmaf(sy, TR.c[id], Pi[j]);
            if (m) {
                Qr[j] = fmaf(dx, TR.s[id], Qr[j]);
                Qi[j] = fmaf(dy, TR.s[id], Qi[j]);
            }
        }
    }
#pragma unroll
    for (int j = 0; j < MC; j++) {
        const int m = M0 + 8 * j;
        if (m == 0) {
            X2[c] = make_float2(Pr[j], Pi[j]);
        } else if (m == 16) {
            X2[16 * 32 + c] = make_float2(Pr[j] - Qi[j], Pi[j] + Qr[j]);
        } else {
            X2[m * 32 + c]        = make_float2(Pr[j] + Qi[j], Pi[j] - Qr[j]);
            X2[(32 - m) * 32 + c] = make_float2(Pr[j] - Qi[j], Pi[j] + Qr[j]);
        }
    }
}

template<int Y0, int Y1>
__device__ __forceinline__ void invH(const float4* __restrict__ sd,
                                     float2* __restrict__ g) {
    constexpr Trig TR = make_trig();
#pragma unroll
    for (int yp = Y0; yp < Y1; yp++) {
        float U1 = 0.f, U2 = 0.f, V1 = 0.f, V2 = 0.f;
#pragma unroll
        for (int p = 0; p < 17; p++) {
            const int id = (p * yp) & 255;
            U1 = fmaf(sd[p].x, TR.c[id], U1);
            U2 = fmaf(sd[p].y, TR.c[id], U2);
            if (p) {
                V1 = fmaf(sd[p].w, TR.s[id], V1);
                V2 = fmaf(sd[p].z, TR.s[id], V2);
            }
        }
        g[(size_t)yp * 512] = make_float2(U1 - V1, U2 + V2);
        if (yp != 0 && yp != 128)
            g[(size_t)(256 - yp) * 512] = make_float2(U1 + V1, U2 - V2);
    }
}

// ---------------------------------------------------------------------------
// k2: per (b,k): fwd H-DFT -> einsum -> pair-combine -> inverse H. 8 warps.
// ---------------------------------------------------------------------------
__global__ void __launch_bounds__(256) k2_mid() {
    __shared__ float2 X2[32 * 32];
    __shared__ float2 OB[32 * 32];
    __shared__ float4 SD[17 * 32];
    int t = threadIdx.x, w = t >> 5, c = t & 31;
    int bk = blockIdx.x;
    int k = bk & 15;

    const float2* __restrict__ xv = g_X1 + (size_t)bk * 8192;   // [y][c]
    switch (w) {
        case 0: phaseA<0, 3>(xv, X2, c); break;   // m = 0, 8, 16
        case 1: phaseA<1, 2>(xv, X2, c); break;
        case 2: phaseA<2, 2>(xv, X2, c); break;
        case 3: phaseA<3, 2>(xv, X2, c); break;
        case 4: phaseA<4, 2>(xv, X2, c); break;
        case 5: phaseA<5, 2>(xv, X2, c); break;
        case 6: phaseA<6, 2>(xv, X2, c); break;
        default: phaseA<7, 2>(xv, X2, c); break;
    }
    __syncthreads();

    // einsum over c: OB[h][o] = sum_c X2[h][c] * Wt[k][h][c][o]; warp w: h=4w..4w+3
    const float2* __restrict__ wtk = g_Wt + (size_t)k * 32768;
#pragma unroll
    for (int j = 0; j < 4; j++) {
        int h = w * 4 + j;
        float ar = 0.f, ai = 0.f;
        const float2* __restrict__ xr = X2 + h * 32;
        const float2* __restrict__ wr = wtk + (size_t)h * 1024 + c;
#pragma unroll
        for (int cc = 0; cc < 32; cc++) {
            float2 xx = xr[cc];
            float2 ww = wr[cc * 32];
            ar = fmaf(xx.x, ww.x, ar); ar = fmaf(-xx.y, ww.y, ar);
            ai = fmaf(xx.x, ww.y, ai); ai = fmaf( xx.y, ww.x, ai);
        }
        OB[h * 32 + c] = make_float2(ar, ai);
    }
    __syncthreads();

    // pair-combine + scale: SD[p][o] = (Sr,Si,Dr,Di)
    float sc = (k == 0) ? (1.0f / 65536.0f) : (2.0f / 65536.0f);
    for (int tt = t; tt < 17 * 32; tt += 256) {
        int p = tt >> 5, o = tt & 31;
        float2 A = OB[p * 32 + o];
        float4 r;
        if (p == 0 || p == 16) {
            r = make_float4(A.x * sc, A.y * sc, -A.x * sc, -A.y * sc);
        } else {
            float2 Bv = OB[(32 - p) * 32 + o];
            r = make_float4((A.x + Bv.x) * sc, (A.y + Bv.y) * sc,
                            (A.x - Bv.x) * sc, (A.y - Bv.y) * sc);
        }
        SD[tt] = r;
    }
    __syncthreads();

    // inverse H: S/D in registers, templated yp ranges per warp
    float4 sd[17];
#pragma unroll
    for (int p = 0; p < 17; p++) sd[p] = SD[p * 32 + c];

    float2* __restrict__ g = g_G + ((size_t)(bk >> 4) * 256 * 16 + k) * 32 + c;
    switch (w) {
        case 0: invH<0,   16>(sd, g); break;
        case 1: invH<16,  32>(sd, g); break;
        case 2: invH<32,  48>(sd, g); break;
        case 3: invH<48,  64>(sd, g); break;
        case 4: invH<64,  80>(sd, g); break;
        case 5: invH<80,  96>(sd, g); break;
        case 6: invH<96, 112>(sd, g); break;
        default: invH<112, 129>(sd, g); break;
    }
}

// ---------------------------------------------------------------------------
// k3: inverse W. Warp per row, lane = o, Gr/Gi in registers, unrolled xp.
// ---------------------------------------------------------------------------
__global__ void __launch_bounds__(256) k3_inv_w(float* __restrict__ out) {
    constexpr Trig TR = make_trig();
    int t = threadIdx.x, o = t & 31;
    int row = blockIdx.x * 8 + (t >> 5);
    const float2* __restrict__ g = g_G + (size_t)row * 512 + o;

    float Gr[16], Gi[16];
#pragma unroll
    for (int k = 0; k < 16; k++) { float2 v = g[k * 32]; Gr[k] = v.x; Gi[k] = v.y; }

    float* __restrict__ ob = out + (size_t)row * 8192 + o;
#pragma unroll
    for (int xp = 0; xp <= 128; xp++) {
        float A = 0.f, B = 0.f;
#pragma unroll
        for (int k = 0; k < 16; k++) {
            const int id = (k * xp) & 255;
            A = fmaf(Gr[k], TR.c[id], A);
            if (k) B = fmaf(Gi[k], TR.s[id], B);
        }
        ob[xp * 32] = A - B;
        if (xp != 0 && xp != 128)
            ob[(256 - xp) * 32] = A + B;
    }
}

// ---------------------------------------------------------------------------
extern "C" void kernel_launch(void* const* d_in, const int* in_sizes, int n_in,
                              void* d_out, int out_size) {
    const float* x  = (const float*)d_in[0];
    const float* wr = (const float*)d_in[1];
    const float* wi = (const float*)d_in[2];
    float* out = (float*)d_out;

    k0_reorder_w<<<2048, 256>>>(wr, wi);
    k1_fwd_w   <<<256, 256>>>(x);
    k2_mid     <<<128, 256>>>();
    k3_inv_w   <<<256, 256>>>(out);
}